// round 3
// baseline (speedup 1.0000x reference)
#include <cuda_runtime.h>

// LearnedBFGSSolver, 3-kernel split:
//  K1: transpose H0 (tiny)
//  K2: per-pair BFGS recursion in low-rank form -> factor vectors A, Un (grid 256)
//  K3: rank-24 epilogue GEMM  H = H0 + S^T A + Un^T S  (grid 1536, high occupancy)

#define NN 192
#define TT 12
#define BE 256
#define NTHREADS 256
#define NWARPS 8

typedef unsigned long long u64;

__device__ float g_H0T[NN * NN];        // H0 transposed
__device__ float g_A [BE * TT * NN];    // A[be][k][j]  = c1_k s_kj - c2_k v_kj
__device__ float g_Un[BE * TT * NN];    // Un[be][k][i] = -c2_k u_ki

__device__ __forceinline__ u64 fma2(u64 a, u64 b, u64 c) {
    u64 d; asm("fma.rn.f32x2 %0, %1, %2, %3;" : "=l"(d) : "l"(a), "l"(b), "l"(c));
    return d;
}
__device__ __forceinline__ u64 pack2(float lo, float hi) {
    u64 d; asm("mov.b64 %0, {%1, %2};" : "=l"(d) : "f"(lo), "f"(hi));
    return d;
}
__device__ __forceinline__ void unpack2(u64 v, float& lo, float& hi) {
    asm("mov.b64 {%0, %1}, %2;" : "=f"(lo), "=f"(hi) : "l"(v));
}

// ---------------- K1: tiled transpose ----------------
__global__ void transpose_kernel(const float* __restrict__ H0g) {
    __shared__ float tile[32][33];
    int bx = blockIdx.x % 6, by = blockIdx.x / 6;
    int x = bx * 32 + threadIdx.x;
    int y = by * 32 + threadIdx.y;
    tile[threadIdx.y][threadIdx.x] = H0g[y * NN + x];
    __syncthreads();
    int xo = by * 32 + threadIdx.x;
    int yo = bx * 32 + threadIdx.y;
    g_H0T[yo * NN + xo] = tile[threadIdx.x][threadIdx.y];
}

// ---------------- K2: recursion -> factor vectors ----------------
struct SmemV {
    float S[TT][NN];
    float Y[TT][NN];
    float U[TT][NN];
    float V[TT][NN];
    u64   Yp[NN][TT / 2];
    float d1[TT], d2[TT], d3[TT], c1[TT], c2[TT];
};

__global__ void __launch_bounds__(NTHREADS, 2)
vectors_kernel(const float* __restrict__ H0g,
               const float* __restrict__ steps,
               const float* __restrict__ dgs)
{
    __shared__ SmemV smv;
    SmemV* sm = &smv;
    const int tid = threadIdx.x;
    const int be  = blockIdx.x;
    const int wid = tid >> 5;
    const int lane = tid & 31;

    for (int idx = tid; idx < TT * NN / 4; idx += NTHREADS) {
        int e = idx * 4;
        int t = e / NN, i = e % NN;
        float4 sv = *reinterpret_cast<const float4*>(&steps[(size_t)(t * BE + be) * NN + i]);
        float4 yv = *reinterpret_cast<const float4*>(&dgs[(size_t)(t * BE + be) * NN + i]);
        *reinterpret_cast<float4*>(&sm->S[t][i]) = sv;
        *reinterpret_cast<float4*>(&sm->Y[t][i]) = yv;
    }
    __syncthreads();

    if (tid < NN) {
        #pragma unroll
        for (int t2 = 0; t2 < TT / 2; t2++)
            sm->Yp[tid][t2] = pack2(sm->Y[2 * t2][tid], sm->Y[2 * t2 + 1][tid]);
    }
    __syncthreads();

    // Phase 1: U[t] = H0 y_t, V[t] = H0^T y_t (coalesced column reads from L2)
    if (tid < NN) {
        const int i = tid;
        u64 p2[TT / 2], q2[TT / 2];
        #pragma unroll
        for (int t2 = 0; t2 < TT / 2; t2++) { p2[t2] = 0ull; q2[t2] = 0ull; }
        const float* __restrict__ hTcol = g_H0T + i;
        const float* __restrict__ hcol  = H0g  + i;
        #pragma unroll 4
        for (int j = 0; j < NN; j++) {
            float hT = __ldg(&hTcol[j * NN]);
            float h  = __ldg(&hcol[j * NN]);
            u64 hT2 = pack2(hT, hT);
            u64 h2  = pack2(h, h);
            #pragma unroll
            for (int t2 = 0; t2 < TT / 2; t2++) {
                u64 y2 = sm->Yp[j][t2];
                p2[t2] = fma2(hT2, y2, p2[t2]);
                q2[t2] = fma2(h2,  y2, q2[t2]);
            }
        }
        #pragma unroll
        for (int t2 = 0; t2 < TT / 2; t2++) {
            unpack2(p2[t2], sm->U[2 * t2][i], sm->U[2 * t2 + 1][i]);
            unpack2(q2[t2], sm->V[2 * t2][i], sm->V[2 * t2 + 1][i]);
        }
    }
    __syncthreads();

    // Phase 2: sequential recursion over t
    for (int t = 0; t < TT; t++) {
        for (int k = wid; k <= t; k += NWARPS) {
            float a1 = 0.f, a2 = 0.f, a3 = 0.f;
            for (int e = lane; e < NN; e += 32) {
                float yv = sm->Y[t][e];
                a1 += sm->S[k][e] * yv;
                if (k < t) {
                    a2 += sm->V[k][e] * yv;
                    a3 += sm->U[k][e] * yv;
                }
            }
            #pragma unroll
            for (int o = 16; o; o >>= 1) {
                a1 += __shfl_xor_sync(0xFFFFFFFFu, a1, o);
                a2 += __shfl_xor_sync(0xFFFFFFFFu, a2, o);
                a3 += __shfl_xor_sync(0xFFFFFFFFu, a3, o);
            }
            if (lane == 0) {
                sm->d1[k] = a1;
                if (k < t) { sm->d2[k] = a2; sm->d3[k] = a3; }
            }
        }
        __syncthreads();

        if (tid < NN) {
            const int i = tid;
            float u = sm->U[t][i];
            float v = sm->V[t][i];
            for (int k = 0; k < t; k++) {
                float c1k = sm->c1[k], c2k = sm->c2[k];
                float dd1 = sm->d1[k];
                float b   = -c2k * dd1;
                float au  = c1k * dd1 - c2k * sm->d2[k];
                float av  = c1k * dd1 - c2k * sm->d3[k];
                float sk  = sm->S[k][i];
                u += au * sk + b * sm->U[k][i];
                v += av * sk + b * sm->V[k][i];
            }
            sm->U[t][i] = u;
            sm->V[t][i] = v;
        }
        __syncthreads();

        if (wid == 0) {
            float a = 0.f;
            for (int e = lane; e < NN; e += 32) a += sm->Y[t][e] * sm->U[t][e];
            #pragma unroll
            for (int o = 16; o; o >>= 1) a += __shfl_xor_sync(0xFFFFFFFFu, a, o);
            if (lane == 0) {
                float sdot = sm->d1[t];
                if (sdot != 0.0f) {
                    float ic = 1.0f / sdot;
                    sm->c2[t] = ic;
                    sm->c1[t] = (sdot + a) * ic * ic;
                } else {
                    sm->c1[t] = 0.0f;
                    sm->c2[t] = 0.0f;
                }
            }
        }
        __syncthreads();
    }

    // Write factor vectors to scratch (coalesced)
    for (int idx = tid; idx < TT * NN; idx += NTHREADS) {
        int k = idx / NN, j = idx % NN;
        float c1k = sm->c1[k], c2k = sm->c2[k];
        g_A [be * TT * NN + idx] = c1k * sm->S[k][j] - c2k * sm->V[k][j];
        g_Un[be * TT * NN + idx] = -c2k * sm->U[k][j];
    }
}

// ---------------- K3: rank-24 epilogue GEMM ----------------
// grid = 256 pairs * 6 row-blocks (32 rows each); 192 threads; 4x8 tiles.
__global__ void __launch_bounds__(192)
epilogue_kernel(const float* __restrict__ H0g,
                const float* __restrict__ steps,
                float* __restrict__ out)
{
    __shared__ float sA[TT][NN];
    __shared__ float sS[TT][NN];
    __shared__ float sUn[TT][32];
    const int tid  = threadIdx.x;
    const int be   = blockIdx.x / 6;
    const int rblk = (blockIdx.x % 6) * 32;

    for (int idx = tid; idx < TT * NN; idx += 192) {
        int k = idx / NN, j = idx % NN;
        sA[k][j] = g_A[be * TT * NN + idx];
        sS[k][j] = steps[(size_t)(k * BE + be) * NN + j];
    }
    for (int idx = tid; idx < TT * 32; idx += 192) {
        int k = idx / 32, r = idx % 32;
        sUn[k][r] = g_Un[be * TT * NN + k * NN + rblk + r];
    }
    __syncthreads();

    const int lr0 = (tid & 7) * 4;      // local row 0..31
    const int c0  = (tid >> 3) * 8;     // col 0..191
    const int grow = rblk + lr0;        // global row
    float* outbase = out + (size_t)be * NN * NN;

    u64 acc[4][4];
    #pragma unroll
    for (int r = 0; r < 4; r++) {
        ulonglong2 h01 = *reinterpret_cast<const ulonglong2*>(&H0g[(grow + r) * NN + c0]);
        ulonglong2 h23 = *reinterpret_cast<const ulonglong2*>(&H0g[(grow + r) * NN + c0 + 4]);
        acc[r][0] = h01.x; acc[r][1] = h01.y; acc[r][2] = h23.x; acc[r][3] = h23.y;
    }
    #pragma unroll
    for (int k = 0; k < TT; k++) {
        ulonglong2 a01 = *reinterpret_cast<ulonglong2*>(&sA[k][c0]);
        ulonglong2 a23 = *reinterpret_cast<ulonglong2*>(&sA[k][c0 + 4]);
        ulonglong2 s01 = *reinterpret_cast<ulonglong2*>(&sS[k][c0]);
        ulonglong2 s23 = *reinterpret_cast<ulonglong2*>(&sS[k][c0 + 4]);
        u64 av[4] = {a01.x, a01.y, a23.x, a23.y};
        u64 sv[4] = {s01.x, s01.y, s23.x, s23.y};
        float4 sr = *reinterpret_cast<float4*>(&sS[k][grow]);
        float4 ur = *reinterpret_cast<float4*>(&sUn[k][lr0]);
        float srow[4] = {sr.x, sr.y, sr.z, sr.w};
        float urow[4] = {ur.x, ur.y, ur.z, ur.w};
        #pragma unroll
        for (int r = 0; r < 4; r++) {
            u64 s2 = pack2(srow[r], srow[r]);
            u64 u2 = pack2(urow[r], urow[r]);
            #pragma unroll
            for (int c = 0; c < 4; c++) {
                acc[r][c] = fma2(s2, av[c], acc[r][c]);
                acc[r][c] = fma2(u2, sv[c], acc[r][c]);
            }
        }
    }
    #pragma unroll
    for (int r = 0; r < 4; r++) {
        *reinterpret_cast<ulonglong2*>(&outbase[(size_t)(grow + r) * NN + c0]) =
            make_ulonglong2(acc[r][0], acc[r][1]);
        *reinterpret_cast<ulonglong2*>(&outbase[(size_t)(grow + r) * NN + c0 + 4]) =
            make_ulonglong2(acc[r][2], acc[r][3]);
    }
}

extern "C" void kernel_launch(void* const* d_in, const int* in_sizes, int n_in,
                              void* d_out, int out_size) {
    const float* H0    = (const float*)d_in[0];   // inv_hessian [192,192]
    const float* steps = (const float*)d_in[1];   // [12,8,32,192]
    const float* dgs   = (const float*)d_in[2];   // [12,8,32,192]
    float* out = (float*)d_out;                   // [8,32,192,192]

    transpose_kernel<<<36, dim3(32, 32)>>>(H0);
    vectors_kernel<<<BE, NTHREADS>>>(H0, steps, dgs);
    epilogue_kernel<<<BE * 6, 192>>>(H0, steps, out);
}

// round 4
// speedup vs baseline: 1.1555x; 1.1555x over previous
#include <cuda_runtime.h>

// LearnedBFGSSolver, 4-kernel pipeline:
//  K1 transpose:  H0T = H0^T (147 KB)
//  K2 kz:         U0 = H0*Y, V0 = H0^T*Y for all 3072 (be,t) rows (big grid GEMV batch)
//  K3 ks:         per-pair: Gram matrices -> 12x12 SCALAR recursion (warp 0) ->
//                 barrier-free per-element rebuild of u,v -> factor vectors A, Un
//  K4 ke:         H = H0 + S^T A + Un^T S  (rank-24 GEMM, grid 768, 8x8 f32x2 tiles)

#define NN 192
#define TT 12
#define BE 256

typedef unsigned long long u64;

__device__ float g_H0T[NN * NN];
__device__ float g_U0[BE * TT * NN];   // u0_t = H0 y_t
__device__ float g_V0[BE * TT * NN];   // v0_t = H0^T y_t
__device__ float g_A [BE * TT * NN];   // A[k][j]  = c1_k s_kj - c2_k v_kj
__device__ float g_Un[BE * TT * NN];   // Un[k][i] = -c2_k u_ki

__device__ __forceinline__ u64 fma2(u64 a, u64 b, u64 c) {
    u64 d; asm("fma.rn.f32x2 %0, %1, %2, %3;" : "=l"(d) : "l"(a), "l"(b), "l"(c));
    return d;
}
__device__ __forceinline__ u64 pack2(float lo, float hi) {
    u64 d; asm("mov.b64 %0, {%1, %2};" : "=l"(d) : "f"(lo), "f"(hi));
    return d;
}
__device__ __forceinline__ void unpack2(u64 v, float& lo, float& hi) {
    asm("mov.b64 {%0, %1}, %2;" : "=f"(lo), "=f"(hi) : "l"(v));
}

// ---------------- K1: tiled transpose ----------------
__global__ void transpose_kernel(const float* __restrict__ H0g) {
    __shared__ float tile[32][33];
    int bx = blockIdx.x % 6, by = blockIdx.x / 6;
    int x = bx * 32 + threadIdx.x;
    int y = by * 32 + threadIdx.y;
    tile[threadIdx.y][threadIdx.x] = H0g[y * NN + x];
    __syncthreads();
    int xo = by * 32 + threadIdx.x;
    int yo = bx * 32 + threadIdx.y;
    g_H0T[yo * NN + xo] = tile[threadIdx.x][threadIdx.y];
}

// ---------------- K2: batched H0*y and H0^T*y, 16 rows per CTA ----------------
// grid 192 (3072 rows / 16), 192 threads (thread = output column i).
__global__ void __launch_bounds__(192)
kz_kernel(const float* __restrict__ H0g, const float* __restrict__ dgs)
{
    __shared__ u64 Yp[NN][8];           // Yp[j][r2] = (Y[r0+2r2][j], Y[r0+2r2+1][j])
    const int tid = threadIdx.x;
    const int r0  = blockIdx.x * 16;    // rows r0..r0+15 share t (256 % 16 == 0)

    #pragma unroll
    for (int r2 = 0; r2 < 8; r2++) {
        int j = tid;
        float lo = dgs[(size_t)(r0 + 2 * r2) * NN + j];
        float hi = dgs[(size_t)(r0 + 2 * r2 + 1) * NN + j];
        Yp[j][r2] = pack2(lo, hi);
    }
    __syncthreads();

    const int i = tid;
    u64 aZ[8], aV[8];
    #pragma unroll
    for (int r2 = 0; r2 < 8; r2++) { aZ[r2] = 0ull; aV[r2] = 0ull; }

    #pragma unroll 4
    for (int j = 0; j < NN; j++) {
        float hT = __ldg(&g_H0T[j * NN + i]);   // = H0[i][j] -> U0
        float h  = __ldg(&H0g [j * NN + i]);    // = H0[j][i] -> V0
        u64 hT2 = pack2(hT, hT);
        u64 h2  = pack2(h, h);
        #pragma unroll
        for (int r2 = 0; r2 < 8; r2++) {
            u64 y2 = Yp[j][r2];
            aZ[r2] = fma2(hT2, y2, aZ[r2]);
            aV[r2] = fma2(h2,  y2, aV[r2]);
        }
    }
    #pragma unroll
    for (int r2 = 0; r2 < 8; r2++) {
        float zlo, zhi, vlo, vhi;
        unpack2(aZ[r2], zlo, zhi);
        unpack2(aV[r2], vlo, vhi);
        int r = r0 + 2 * r2;
        int t = r / BE, be = r % BE;
        g_U0[(size_t)(be * TT + t) * NN + i]       = zlo;
        g_U0[(size_t)((be + 1) * TT + t) * NN + i] = zhi;
        g_V0[(size_t)(be * TT + t) * NN + i]       = vlo;
        g_V0[(size_t)((be + 1) * TT + t) * NN + i] = vhi;
    }
}

// ---------------- K3: per-pair scalar recursion + factor vectors ----------------
__global__ void __launch_bounds__(192)
ks_kernel(const float* __restrict__ steps, const float* __restrict__ dgs)
{
    __shared__ float sS[TT][NN], sY[TT][NN], sU0[TT][NN], sV0[TT][NN];
    __shared__ float sG1[TT][TT], sW[TT][TT];
    __shared__ float sCU[TT][TT], sCV[TT][TT], sB[TT][TT];
    __shared__ float sC1[TT], sC2[TT];

    const int tid = threadIdx.x;
    const int be  = blockIdx.x;

    for (int idx = tid; idx < TT * NN / 4; idx += 192) {
        int e = idx * 4;
        int k = e / NN, j = e % NN;
        *(float4*)&sS[k][j]  = *(const float4*)&steps[(size_t)(k * BE + be) * NN + j];
        *(float4*)&sY[k][j]  = *(const float4*)&dgs  [(size_t)(k * BE + be) * NN + j];
        *(float4*)&sU0[k][j] = *(const float4*)&g_U0[(size_t)(be * TT + k) * NN + j];
        *(float4*)&sV0[k][j] = *(const float4*)&g_V0[(size_t)(be * TT + k) * NN + j];
    }
    __syncthreads();

    // ---- Grams: G1 = S Y^T, W = V0 Y^T, 2x2 cells per thread (72 threads) ----
    if (tid < 72) {
        int which = tid / 36;             // 0 -> G1, 1 -> W
        int cell  = tid % 36;
        int k0 = (cell / 6) * 2, t0 = (cell % 6) * 2;
        const float (*P)[NN] = which ? sV0 : sS;
        float a00 = 0.f, a01 = 0.f, a10 = 0.f, a11 = 0.f;
        for (int j = 0; j < NN; j += 4) {
            float4 p0 = *(const float4*)&P[k0][j];
            float4 p1 = *(const float4*)&P[k0 + 1][j];
            float4 q0 = *(const float4*)&sY[t0][j];
            float4 q1 = *(const float4*)&sY[t0 + 1][j];
            a00 += p0.x * q0.x + p0.y * q0.y + p0.z * q0.z + p0.w * q0.w;
            a01 += p0.x * q1.x + p0.y * q1.y + p0.z * q1.z + p0.w * q1.w;
            a10 += p1.x * q0.x + p1.y * q0.y + p1.z * q0.z + p1.w * q0.w;
            a11 += p1.x * q1.x + p1.y * q1.y + p1.z * q1.z + p1.w * q1.w;
        }
        float (*G)[TT] = which ? sW : sG1;
        G[k0][t0] = a00;     G[k0][t0 + 1] = a01;
        G[k0 + 1][t0] = a10; G[k0 + 1][t0 + 1] = a11;
    }
    __syncthreads();

    // ---- Warp-0 scalar recursion, lane = column t ----
    if (tid < 32) {
        const int t = (tid < TT) ? tid : (TT - 1);
        float G1c[TT], Wc[TT], Wr[TT];
        float d2c[TT], d3c[TT];            // d2 = v-dot, d3 = u-dot (column t)
        float c1v[TT], c2v[TT];
        float cuL[TT], cvL[TT], bL[TT];    // coefs with superscript (t)
        #pragma unroll
        for (int m = 0; m < TT; m++) {
            G1c[m] = sG1[m][t];
            Wc[m]  = sW[m][t];             // base of d2[m][t]
            Wr[m]  = sW[t][m];             // base of d3[m][t]
            cuL[m] = 0.f; cvL[m] = 0.f; bL[m] = 0.f;
        }
        #pragma unroll
        for (int k = 0; k < TT; k++) {
            if (k > 0) {
                const int m = k - 1;       // c's for m now final -> freeze coefs
                cuL[m] = c1v[m] * G1c[m] - c2v[m] * d2c[m];  // multiplies s_m in u-update
                cvL[m] = c1v[m] * G1c[m] - c2v[m] * d3c[m];  // multiplies s_m in v-update
                bL[m]  = -c2v[m] * G1c[m];
            }
            float x2 = Wc[k], x3 = Wr[k];
            #pragma unroll
            for (int m = 0; m < TT - 1; m++) {
                if (m < k) {
                    float cvk = __shfl_sync(0xFFFFFFFFu, cvL[m], k);
                    float cuk = __shfl_sync(0xFFFFFFFFu, cuL[m], k);
                    float bk  = __shfl_sync(0xFFFFFFFFu, bL[m],  k);
                    x2 += cvk * G1c[m] + bk * d2c[m];
                    x3 += cuk * G1c[m] + bk * d3c[m];
                }
            }
            d2c[k] = x2;
            d3c[k] = x3;
            float yHy  = __shfl_sync(0xFFFFFFFFu, x3, k);      // d3[k][k] = y_k.u_k
            float sdot = __shfl_sync(0xFFFFFFFFu, G1c[k], k);  // s_k.y_k
            float ic = (sdot != 0.0f) ? (1.0f / sdot) : 0.0f;
            c2v[k] = ic;
            c1v[k] = (sdot + yHy) * ic * ic;
        }
        if (tid < TT) {
            #pragma unroll
            for (int m = 0; m < TT - 1; m++) {
                sCU[m][t] = cuL[m];
                sCV[m][t] = cvL[m];
                sB[m][t]  = bL[m];
            }
        }
        if (tid == 0) {
            #pragma unroll
            for (int m = 0; m < TT; m++) { sC1[m] = c1v[m]; sC2[m] = c2v[m]; }
        }
    }
    __syncthreads();

    // ---- Barrier-free per-element rebuild of u_t, v_t; emit A, Un ----
    {
        const int i = tid;
        float s[TT], u[TT], v[TT];
        #pragma unroll
        for (int k = 0; k < TT; k++) {
            s[k] = sS[k][i];
            u[k] = sU0[k][i];
            v[k] = sV0[k][i];
        }
        #pragma unroll
        for (int t = 0; t < TT; t++) {
            #pragma unroll
            for (int k = 0; k < TT - 1; k++) {
                if (k < t) {
                    float bb = sB[k][t];
                    u[t] += sCU[k][t] * s[k] + bb * u[k];
                    v[t] += sCV[k][t] * s[k] + bb * v[k];
                }
            }
            float c1 = sC1[t], c2 = sC2[t];
            g_A [(size_t)(be * TT + t) * NN + i] = c1 * s[t] - c2 * v[t];
            g_Un[(size_t)(be * TT + t) * NN + i] = -c2 * u[t];
        }
    }
}

// ---------------- K4: rank-24 epilogue GEMM ----------------
// grid = 256 pairs * 3 row-blocks (64 rows); 192 threads; 8x8 f32x2 tiles.
__global__ void __launch_bounds__(192)
ke_kernel(const float* __restrict__ H0g,
          const float* __restrict__ steps,
          float* __restrict__ out)
{
    __shared__ float sA[TT][NN];
    __shared__ float sS[TT][NN];
    __shared__ float sUn[TT][64];
    const int tid  = threadIdx.x;
    const int be   = blockIdx.x / 3;
    const int rblk = (blockIdx.x % 3) * 64;

    for (int idx = tid; idx < TT * NN / 4; idx += 192) {
        int e = idx * 4;
        int k = e / NN, j = e % NN;
        *(float4*)&sA[k][j] = *(const float4*)&g_A[(size_t)(be * TT + k) * NN + j];
        *(float4*)&sS[k][j] = *(const float4*)&steps[(size_t)(k * BE + be) * NN + j];
    }
    for (int idx = tid; idx < TT * 64 / 4; idx += 192) {
        int e = idx * 4;
        int k = e / 64, r = e % 64;
        *(float4*)&sUn[k][r] = *(const float4*)&g_Un[(size_t)(be * TT + k) * NN + rblk + r];
    }
    __syncthreads();

    const int cg = tid % 24, rg = tid / 24;
    const int c0 = cg * 8;
    const int lr0 = rg * 8;
    const int grow = rblk + lr0;
    float* ob = out + (size_t)be * NN * NN;

    u64 acc[8][4];
    #pragma unroll
    for (int r = 0; r < 8; r++) {
        ulonglong2 h01 = *(const ulonglong2*)&H0g[(size_t)(grow + r) * NN + c0];
        ulonglong2 h23 = *(const ulonglong2*)&H0g[(size_t)(grow + r) * NN + c0 + 4];
        acc[r][0] = h01.x; acc[r][1] = h01.y; acc[r][2] = h23.x; acc[r][3] = h23.y;
    }
    #pragma unroll
    for (int k = 0; k < TT; k++) {
        ulonglong2 a01 = *(ulonglong2*)&sA[k][c0];
        ulonglong2 a23 = *(ulonglong2*)&sA[k][c0 + 4];
        ulonglong2 s01 = *(ulonglong2*)&sS[k][c0];
        ulonglong2 s23 = *(ulonglong2*)&sS[k][c0 + 4];
        u64 av[4] = {a01.x, a01.y, a23.x, a23.y};
        u64 sv[4] = {s01.x, s01.y, s23.x, s23.y};
        float4 sr0 = *(float4*)&sS[k][grow];
        float4 sr1 = *(float4*)&sS[k][grow + 4];
        float4 ur0 = *(float4*)&sUn[k][lr0];
        float4 ur1 = *(float4*)&sUn[k][lr0 + 4];
        float srow[8] = {sr0.x, sr0.y, sr0.z, sr0.w, sr1.x, sr1.y, sr1.z, sr1.w};
        float urow[8] = {ur0.x, ur0.y, ur0.z, ur0.w, ur1.x, ur1.y, ur1.z, ur1.w};
        #pragma unroll
        for (int r = 0; r < 8; r++) {
            u64 s2 = pack2(srow[r], srow[r]);
            u64 u2 = pack2(urow[r], urow[r]);
            #pragma unroll
            for (int c = 0; c < 4; c++) {
                acc[r][c] = fma2(s2, av[c], acc[r][c]);
                acc[r][c] = fma2(u2, sv[c], acc[r][c]);
            }
        }
    }
    #pragma unroll
    for (int r = 0; r < 8; r++) {
        *(ulonglong2*)&ob[(size_t)(grow + r) * NN + c0] =
            make_ulonglong2(acc[r][0], acc[r][1]);
        *(ulonglong2*)&ob[(size_t)(grow + r) * NN + c0 + 4] =
            make_ulonglong2(acc[r][2], acc[r][3]);
    }
}

extern "C" void kernel_launch(void* const* d_in, const int* in_sizes, int n_in,
                              void* d_out, int out_size) {
    const float* H0    = (const float*)d_in[0];   // inv_hessian [192,192]
    const float* steps = (const float*)d_in[1];   // [12,8,32,192]
    const float* dgs   = (const float*)d_in[2];   // [12,8,32,192]
    float* out = (float*)d_out;                   // [8,32,192,192]

    transpose_kernel<<<36, dim3(32, 32)>>>(H0);
    kz_kernel<<<192, 192>>>(H0, dgs);
    ks_kernel<<<BE, 192>>>(steps, dgs);
    ke_kernel<<<BE * 3, 192>>>(H0, steps, out);
}